// round 4
// baseline (speedup 1.0000x reference)
#include <cuda_runtime.h>
#include <cuda_bf16.h>
#include <cstdint>

// Problem constants
#define B_LON   15
#define NW      64
#define NTOK    144
#define DIM     192
#define NH      6
#define HD      32
#define MROWS   (B_LON * NW * NTOK)   // 138240
#define QKV_N   (3 * DIM)             // 576

// Scratch (allocation-free rule: __device__ globals)
__device__ float g_qkv[(size_t)B_LON * NW * NTOK * QKV_N];  // 79,626,240 floats
__device__ float g_att[(size_t)B_LON * NW * NTOK * DIM];    // 26,542,080 floats

// ---------------------------------------------------------------------------
// Generic tiled fp32 GEMM with bias: C[M,N] = A[M,K] * B[K,N] + bias[N]
// BM=128, BN=64, BK=16, 256 threads, 8x4 per-thread tile.
// Requires M%128==0, N%64==0, K%16==0 (true for all uses here).
// ---------------------------------------------------------------------------
__global__ __launch_bounds__(256) void gemm_bias_kernel(
    const float* __restrict__ A, const float* __restrict__ B,
    const float* __restrict__ bias, float* __restrict__ C,
    int M, int N, int K)
{
    __shared__ float As[16 * 128];   // [k][m]
    __shared__ float Bs[16 * 64];    // [k][n]

    const int tx = threadIdx.x & 15;   // N dim: 16*4 = 64
    const int ty = threadIdx.x >> 4;   // M dim: 16*8 = 128
    const int m0 = blockIdx.y * 128;
    const int n0 = blockIdx.x * 64;

    float acc[8][4];
#pragma unroll
    for (int i = 0; i < 8; i++)
#pragma unroll
        for (int j = 0; j < 4; j++) acc[i][j] = 0.0f;

    for (int k0 = 0; k0 < K; k0 += 16) {
        // Load A tile (128x16) transposed into As[k][m]
#pragma unroll
        for (int s = 0; s < 2; s++) {
            int idx = threadIdx.x * 2 + s;     // 0..511 float4 slots
            int r = idx >> 2;                  // 0..127
            int c = (idx & 3) * 4;             // 0,4,8,12
            float4 a4 = *(const float4*)(A + (size_t)(m0 + r) * K + k0 + c);
            As[(c + 0) * 128 + r] = a4.x;
            As[(c + 1) * 128 + r] = a4.y;
            As[(c + 2) * 128 + r] = a4.z;
            As[(c + 3) * 128 + r] = a4.w;
        }
        // Load B tile (16x64)
        {
            int r  = threadIdx.x >> 4;         // 0..15
            int c  = (threadIdx.x & 15) * 4;   // 0..60
            *(float4*)(Bs + r * 64 + c) =
                *(const float4*)(B + (size_t)(k0 + r) * N + n0 + c);
        }
        __syncthreads();

#pragma unroll
        for (int kk = 0; kk < 16; kk++) {
            float a[8], b[4];
#pragma unroll
            for (int i = 0; i < 8; i++) a[i] = As[kk * 128 + ty * 8 + i];
#pragma unroll
            for (int j = 0; j < 4; j++) b[j] = Bs[kk * 64 + tx * 4 + j];
#pragma unroll
            for (int i = 0; i < 8; i++)
#pragma unroll
                for (int j = 0; j < 4; j++) acc[i][j] += a[i] * b[j];
        }
        __syncthreads();
    }

    float4 bv = *(const float4*)(bias + n0 + tx * 4);
#pragma unroll
    for (int i = 0; i < 8; i++) {
        float4 o;
        o.x = acc[i][0] + bv.x;
        o.y = acc[i][1] + bv.y;
        o.z = acc[i][2] + bv.z;
        o.w = acc[i][3] + bv.w;
        *(float4*)(C + (size_t)(m0 + ty * 8 + i) * N + n0 + tx * 4) = o;
    }
}

// ---------------------------------------------------------------------------
// Fused per-(b, w, h) attention:
//   S = (q*scale) k^T + bias(pos_index) + mask ; P = softmax(S) ; O = P v
// Earth position index decomposes additively: idx = f(n) + g(m) with
//   n -> (zi,hi,wi): f = 828*zi + 23*hi + wi
//   m -> (zj,hj,wj): g = 1656*zj + 138*hj - wj + 11
// Bias slice for (w,h) (3312 floats) preloaded into smem.
// ---------------------------------------------------------------------------
#define QT_PITCH 148
#define S_PITCH  145
// floats: 2*32*148 + 144*32 + 144*145 + 144 + 3312 = 38416 ; + 288 ints
#define ATT_SMEM_FLOATS (2*32*QT_PITCH + NTOK*HD + NTOK*S_PITCH + NTOK + 3312)
#define ATT_SMEM_BYTES  (ATT_SMEM_FLOATS*4 + 2*NTOK*4)

__global__ __launch_bounds__(256) void attn_kernel(
    const float* __restrict__ qkv, const float* __restrict__ mask,
    const float* __restrict__ bias_table, float* __restrict__ out)
{
    extern __shared__ float sm[];
    float* qT    = sm;                       // [32][148]  (scaled q, transposed)
    float* kT    = qT + 32 * QT_PITCH;       // [32][148]
    float* vS    = kT + 32 * QT_PITCH;       // [144][32]
    float* S     = vS + NTOK * HD;           // [144][145]
    float* rsum  = S + NTOK * S_PITCH;       // [144]
    float* sbias = rsum + NTOK;              // [3312]
    int*   fI    = (int*)(sbias + 3312);     // [144]
    int*   gI    = fI + NTOK;                // [144]

    const int w = blockIdx.x, b = blockIdx.y, h = blockIdx.z;
    const int tid = threadIdx.x;
    const int bw = b * NW + w;
    const float* base = qkv + (size_t)bw * NTOK * QKV_N;
    const float scale = 0.17677669529663687f;  // 1/sqrt(32)

    // Stage q (scaled, transposed), k (transposed), v into smem
    for (int idx = tid; idx < NTOK * 8; idx += 256) {
        int n = idx >> 3;
        int d = (idx & 7) * 4;
        const float* p = base + n * QKV_N + h * HD + d;
        float4 q4 = *(const float4*)(p);
        float4 k4 = *(const float4*)(p + DIM);
        float4 v4 = *(const float4*)(p + 2 * DIM);
        qT[(d + 0) * QT_PITCH + n] = q4.x * scale;
        qT[(d + 1) * QT_PITCH + n] = q4.y * scale;
        qT[(d + 2) * QT_PITCH + n] = q4.z * scale;
        qT[(d + 3) * QT_PITCH + n] = q4.w * scale;
        kT[(d + 0) * QT_PITCH + n] = k4.x;
        kT[(d + 1) * QT_PITCH + n] = k4.y;
        kT[(d + 2) * QT_PITCH + n] = k4.z;
        kT[(d + 3) * QT_PITCH + n] = k4.w;
        *(float4*)(vS + n * HD + d) = v4;
    }
    // Preload bias slice for this (w, h): bias_table[idx][w][h], idx<3312
    {
        const int wh = w * NH + h;
        for (int i = tid; i < 3312; i += 256)
            sbias[i] = bias_table[(size_t)i * (NW * NH) + wh];
    }
    if (tid < NTOK) {
        int zi = tid / 72, hi = (tid / 12) % 6, wi = tid % 12;
        fI[tid] = 828 * zi + 23 * hi + wi;
        gI[tid] = 1656 * zi + 138 * hi - wi + 11;
    }
    __syncthreads();

    // Phase 2: S[n][m] = q.k + bias + mask   (16x16 threads, 9x9 per thread)
    {
        const int tx = tid & 15, ty = tid >> 4;
        float acc[9][9];
#pragma unroll
        for (int i = 0; i < 9; i++)
#pragma unroll
            for (int j = 0; j < 9; j++) acc[i][j] = 0.0f;

#pragma unroll 4
        for (int d = 0; d < HD; d++) {
            float qv[9], kv[9];
#pragma unroll
            for (int i = 0; i < 9; i++) qv[i] = qT[d * QT_PITCH + ty + 16 * i];
#pragma unroll
            for (int j = 0; j < 9; j++) kv[j] = kT[d * QT_PITCH + tx + 16 * j];
#pragma unroll
            for (int i = 0; i < 9; i++)
#pragma unroll
                for (int j = 0; j < 9; j++) acc[i][j] += qv[i] * kv[j];
        }
        const float* mrow = mask + (size_t)bw * NTOK * NTOK;
#pragma unroll
        for (int i = 0; i < 9; i++) {
            int n = ty + 16 * i;
            int fn = fI[n];
#pragma unroll
            for (int j = 0; j < 9; j++) {
                int m = tx + 16 * j;
                S[n * S_PITCH + m] = acc[i][j] + sbias[fn + gI[m]] + mrow[n * NTOK + m];
            }
        }
    }
    __syncthreads();

    // Phase 3: row softmax (thread t owns row t); keep exp values, store 1/sum
    if (tid < NTOK) {
        float* row = S + tid * S_PITCH;
        float mx = row[0];
        for (int m = 1; m < NTOK; m++) mx = fmaxf(mx, row[m]);
        float s = 0.0f;
        for (int m = 0; m < NTOK; m++) {
            float e = __expf(row[m] - mx);
            row[m] = e;
            s += e;
        }
        rsum[tid] = 1.0f / s;
    }
    __syncthreads();

    // Phase 4: O = P v  (32 d-threads x 8 row-groups, 18 rows/thread)
    {
        const int dx = tid & 31, ny = tid >> 5;
        float o[18];
#pragma unroll
        for (int k = 0; k < 18; k++) o[k] = 0.0f;
        for (int m = 0; m < NTOK; m++) {
            float vv = vS[m * HD + dx];
#pragma unroll
            for (int k = 0; k < 18; k++)
                o[k] += S[(ny + 8 * k) * S_PITCH + m] * vv;
        }
        float* ob = out + (size_t)bw * NTOK * DIM + h * HD + dx;
#pragma unroll
        for (int k = 0; k < 18; k++) {
            int n = ny + 8 * k;
            ob[(size_t)n * DIM] = o[k] * rsum[n];
        }
    }
}

// ---------------------------------------------------------------------------
extern "C" void kernel_launch(void* const* d_in, const int* in_sizes, int n_in,
                              void* d_out, int out_size)
{
    const float* x          = (const float*)d_in[0];
    const float* mask       = (const float*)d_in[1];
    const float* qkv_w      = (const float*)d_in[2];
    const float* qkv_b      = (const float*)d_in[3];
    const float* proj_w     = (const float*)d_in[4];
    const float* proj_b     = (const float*)d_in[5];
    const float* bias_table = (const float*)d_in[6];
    float* out = (float*)d_out;

    float *qkv_s, *att_s;
    cudaGetSymbolAddress((void**)&qkv_s, g_qkv);
    cudaGetSymbolAddress((void**)&att_s, g_att);

    cudaFuncSetAttribute(attn_kernel,
                         cudaFuncAttributeMaxDynamicSharedMemorySize,
                         ATT_SMEM_BYTES);

    // 1) QKV projection: (138240 x 192) @ (192 x 576) + b
    gemm_bias_kernel<<<dim3(QKV_N / 64, MROWS / 128), 256>>>(
        x, qkv_w, qkv_b, qkv_s, MROWS, QKV_N, DIM);

    // 2) Fused windowed attention per (w, b, h)
    attn_kernel<<<dim3(NW, B_LON, NH), 256, ATT_SMEM_BYTES>>>(
        qkv_s, mask, bias_table, att_s);

    // 3) Output projection: (138240 x 192) @ (192 x 192) + b
    gemm_bias_kernel<<<dim3(DIM / 64, MROWS / 128), 256>>>(
        att_s, proj_w, proj_b, out, MROWS, DIM, DIM);
}

// round 5
// speedup vs baseline: 1.2300x; 1.2300x over previous
#include <cuda_runtime.h>
#include <cuda_bf16.h>
#include <cstdint>

// Problem constants
#define B_LON   15
#define NW      64
#define NTOK    144
#define DIM     192
#define NH      6
#define HD      32
#define MROWS   (B_LON * NW * NTOK)   // 138240
#define QKV_N   (3 * DIM)             // 576
#define NBIAS   3312

// Scratch (allocation-free rule: __device__ globals)
__device__ float g_qkv[(size_t)B_LON * NW * NTOK * QKV_N];   // 318 MB
__device__ float g_att[(size_t)B_LON * NW * NTOK * DIM];     // 106 MB
__device__ float g_biasT[(size_t)NW * NH * NBIAS];           // 5 MB: [w*NH+h][idx]

// ---------------------------------------------------------------------------
// Bias table transpose: g_biasT[wh][idx] = bias_table[idx][wh]
// grid = NBIAS blocks x 384 threads (coalesced reads)
// ---------------------------------------------------------------------------
__global__ void bias_transpose_kernel(const float* __restrict__ bias_table,
                                      float* __restrict__ biasT)
{
    int idx = blockIdx.x;          // 0..3311
    int wh  = threadIdx.x;         // 0..383
    biasT[(size_t)wh * NBIAS + idx] = bias_table[(size_t)idx * (NW * NH) + wh];
}

// ---------------------------------------------------------------------------
// fp32 GEMM + bias: C[M,N] = A[M,K] * B[K,N] + bias[N]
// BM=128, BN=64, BK=16, 128 threads, 8x8 per-thread tile, float4 smem reads,
// register-prefetch of the next K tile. Requires M%128==0, N%64==0, K%16==0.
// ---------------------------------------------------------------------------
#define BM 128
#define BN 64
#define BK 16
#define A_PITCH 132   // mult of 4 (float4 align), 2-way max STS conflict

__global__ __launch_bounds__(128, 3) void gemm_bias_kernel(
    const float* __restrict__ A, const float* __restrict__ B,
    const float* __restrict__ bias, float* __restrict__ C,
    int M, int N, int K)
{
    __shared__ float As[BK * A_PITCH];   // [k][m]
    __shared__ float Bs[BK * BN];        // [k][n]

    const int tid = threadIdx.x;
    const int tx = tid & 7;              // 8 col groups
    const int ty = tid >> 3;             // 16 row groups
    const int m0 = blockIdx.y * BM;
    const int n0 = blockIdx.x * BN;

    // A load mapping: s=0..3 -> row r = s*32 + (tid>>2), col c = (tid&3)*4
    const int ar = tid >> 2;
    const int ac = (tid & 3) * 4;
    const float* Ap = A + (size_t)(m0 + ar) * K + ac;
    // B load mapping: s=0..1 -> row r = s*8 + (tid>>4), col = (tid&15)*4
    const int br = tid >> 4;
    const int bc = (tid & 15) * 4;
    const float* Bp = B + (size_t)br * N + n0 + bc;

    float acc[8][8];
#pragma unroll
    for (int i = 0; i < 8; i++)
#pragma unroll
        for (int j = 0; j < 8; j++) acc[i][j] = 0.0f;

    const int T = K / BK;
    float4 pa[4], pb[2];

    // Prologue: load + store tile 0
#pragma unroll
    for (int s = 0; s < 4; s++) pa[s] = *(const float4*)(Ap + (size_t)s * 32 * K);
#pragma unroll
    for (int s = 0; s < 2; s++) pb[s] = *(const float4*)(Bp + (size_t)s * 8 * N);
#pragma unroll
    for (int s = 0; s < 4; s++) {
        int r = s * 32 + ar;
        As[(ac + 0) * A_PITCH + r] = pa[s].x;
        As[(ac + 1) * A_PITCH + r] = pa[s].y;
        As[(ac + 2) * A_PITCH + r] = pa[s].z;
        As[(ac + 3) * A_PITCH + r] = pa[s].w;
    }
#pragma unroll
    for (int s = 0; s < 2; s++)
        *(float4*)&Bs[(s * 8 + br) * BN + bc] = pb[s];

    for (int t = 0; t < T; t++) {
        __syncthreads();   // smem tile t ready

        if (t + 1 < T) {   // prefetch tile t+1 into registers
            const float* Ap2 = Ap + (t + 1) * BK;
            const float* Bp2 = Bp + (size_t)(t + 1) * BK * N;
#pragma unroll
            for (int s = 0; s < 4; s++) pa[s] = *(const float4*)(Ap2 + (size_t)s * 32 * K);
#pragma unroll
            for (int s = 0; s < 2; s++) pb[s] = *(const float4*)(Bp2 + (size_t)s * 8 * N);
        }

#pragma unroll
        for (int kk = 0; kk < BK; kk++) {
            float4 a0 = *(float4*)&As[kk * A_PITCH + ty * 4];
            float4 a1 = *(float4*)&As[kk * A_PITCH + 64 + ty * 4];
            float4 b0 = *(float4*)&Bs[kk * BN + tx * 4];
            float4 b1 = *(float4*)&Bs[kk * BN + 32 + tx * 4];
            float a[8] = {a0.x, a0.y, a0.z, a0.w, a1.x, a1.y, a1.z, a1.w};
            float b[8] = {b0.x, b0.y, b0.z, b0.w, b1.x, b1.y, b1.z, b1.w};
#pragma unroll
            for (int i = 0; i < 8; i++)
#pragma unroll
                for (int j = 0; j < 8; j++) acc[i][j] += a[i] * b[j];
        }

        __syncthreads();   // compute done, safe to overwrite smem

        if (t + 1 < T) {
#pragma unroll
            for (int s = 0; s < 4; s++) {
                int r = s * 32 + ar;
                As[(ac + 0) * A_PITCH + r] = pa[s].x;
                As[(ac + 1) * A_PITCH + r] = pa[s].y;
                As[(ac + 2) * A_PITCH + r] = pa[s].z;
                As[(ac + 3) * A_PITCH + r] = pa[s].w;
            }
#pragma unroll
            for (int s = 0; s < 2; s++)
                *(float4*)&Bs[(s * 8 + br) * BN + bc] = pb[s];
        }
    }

    float4 bv0 = *(const float4*)(bias + n0 + tx * 4);
    float4 bv1 = *(const float4*)(bias + n0 + 32 + tx * 4);
#pragma unroll
    for (int i = 0; i < 8; i++) {
        int row = m0 + ((i < 4) ? (ty * 4 + i) : (64 + ty * 4 + i - 4));
        float4 o0, o1;
        o0.x = acc[i][0] + bv0.x; o0.y = acc[i][1] + bv0.y;
        o0.z = acc[i][2] + bv0.z; o0.w = acc[i][3] + bv0.w;
        o1.x = acc[i][4] + bv1.x; o1.y = acc[i][5] + bv1.y;
        o1.z = acc[i][6] + bv1.z; o1.w = acc[i][7] + bv1.w;
        *(float4*)(C + (size_t)row * N + n0 + tx * 4) = o0;
        *(float4*)(C + (size_t)row * N + n0 + 32 + tx * 4) = o1;
    }
}

// ---------------------------------------------------------------------------
// Fused per-(b, w, h) attention.
// Earth position index decomposes additively: idx = f(n) + g(m) with
//   n -> (zi,hi,wi): f = 828*zi + 23*hi + wi
//   m -> (zj,hj,wj): g = 1656*zj + 138*hj - wj + 11
// ---------------------------------------------------------------------------
#define QT_PITCH 148
#define S_PITCH  148
#define ATT_SMEM_FLOATS (2*32*QT_PITCH + NTOK*HD + NTOK*S_PITCH + NTOK + NBIAS)
#define ATT_SMEM_BYTES  (ATT_SMEM_FLOATS*4 + 2*NTOK*4)

__global__ __launch_bounds__(256) void attn_kernel(
    const float* __restrict__ qkv, const float* __restrict__ mask,
    const float* __restrict__ biasT, float* __restrict__ out)
{
    extern __shared__ float sm[];
    float* qT    = sm;                       // [32][148] scaled q, transposed
    float* kT    = qT + 32 * QT_PITCH;       // [32][148]
    float* vS    = kT + 32 * QT_PITCH;       // [144][32]
    float* S     = vS + NTOK * HD;           // [144][148]
    float* rsum  = S + NTOK * S_PITCH;       // [144]
    float* sbias = rsum + NTOK;              // [3312]
    int*   fI    = (int*)(sbias + NBIAS);    // [144]
    int*   gI    = fI + NTOK;                // [144]

    const int w = blockIdx.x, b = blockIdx.y, h = blockIdx.z;
    const int tid = threadIdx.x;
    const int bw = b * NW + w;
    const float* base = qkv + (size_t)bw * NTOK * QKV_N;
    const float scale = 0.17677669529663687f;  // 1/sqrt(32)

    // Stage q (scaled, transposed), k (transposed), v
    for (int idx = tid; idx < NTOK * 8; idx += 256) {
        int n = idx >> 3;
        int d = (idx & 7) * 4;
        const float* p = base + n * QKV_N + h * HD + d;
        float4 q4 = *(const float4*)(p);
        float4 k4 = *(const float4*)(p + DIM);
        float4 v4 = *(const float4*)(p + 2 * DIM);
        qT[(d + 0) * QT_PITCH + n] = q4.x * scale;
        qT[(d + 1) * QT_PITCH + n] = q4.y * scale;
        qT[(d + 2) * QT_PITCH + n] = q4.z * scale;
        qT[(d + 3) * QT_PITCH + n] = q4.w * scale;
        kT[(d + 0) * QT_PITCH + n] = k4.x;
        kT[(d + 1) * QT_PITCH + n] = k4.y;
        kT[(d + 2) * QT_PITCH + n] = k4.z;
        kT[(d + 3) * QT_PITCH + n] = k4.w;
        *(float4*)(vS + n * HD + d) = v4;
    }
    // Bias slice for (w,h): contiguous after pre-transpose, float4 loads
    {
        const float* bsrc = biasT + (size_t)(w * NH + h) * NBIAS;
        for (int i = tid * 4; i < NBIAS; i += 1024)
            *(float4*)(sbias + i) = *(const float4*)(bsrc + i);
    }
    if (tid < NTOK) {
        int zi = tid / 72, hi = (tid / 12) % 6, wi = tid % 12;
        fI[tid] = 828 * zi + 23 * hi + wi;
        gI[tid] = 1656 * zi + 138 * hi - wi + 11;
    }
    __syncthreads();

    // Phase 2: S[n][m] = q.k + bias + mask   (16x16 threads, 9x9 per thread)
    {
        const int tx = tid & 15, ty = tid >> 4;
        float acc[9][9];
#pragma unroll
        for (int i = 0; i < 9; i++)
#pragma unroll
            for (int j = 0; j < 9; j++) acc[i][j] = 0.0f;

#pragma unroll 4
        for (int d = 0; d < HD; d++) {
            float qv[9], kv[9];
#pragma unroll
            for (int i = 0; i < 9; i++) qv[i] = qT[d * QT_PITCH + ty + 16 * i];
#pragma unroll
            for (int j = 0; j < 9; j++) kv[j] = kT[d * QT_PITCH + tx + 16 * j];
#pragma unroll
            for (int i = 0; i < 9; i++)
#pragma unroll
                for (int j = 0; j < 9; j++) acc[i][j] += qv[i] * kv[j];
        }
        const float* mrow = mask + (size_t)bw * NTOK * NTOK;
        int gm[9];
#pragma unroll
        for (int j = 0; j < 9; j++) gm[j] = gI[tx + 16 * j];
#pragma unroll
        for (int i = 0; i < 9; i++) {
            int n = ty + 16 * i;
            int fn = fI[n];
#pragma unroll
            for (int j = 0; j < 9; j++) {
                int m = tx + 16 * j;
                S[n * S_PITCH + m] = acc[i][j] + sbias[fn + gm[j]] + mrow[n * NTOK + m];
            }
        }
    }
    __syncthreads();

    // Phase 3: warp-parallel softmax. 8 warps x 18 rows, shfl reductions.
    {
        const int wp = tid >> 5, lane = tid & 31;
        for (int i = 0; i < 18; i++) {
            int r = wp * 18 + i;
            float* row = S + r * S_PITCH;
            float v0 = row[lane];
            float v1 = row[lane + 32];
            float v2 = row[lane + 64];
            float v3 = row[lane + 96];
            float v4 = (lane < 16) ? row[lane + 128] : -1e30f;
            float mx = fmaxf(fmaxf(fmaxf(v0, v1), fmaxf(v2, v3)), v4);
#pragma unroll
            for (int off = 16; off > 0; off >>= 1)
                mx = fmaxf(mx, __shfl_xor_sync(0xffffffffu, mx, off));
            float e0 = __expf(v0 - mx);
            float e1 = __expf(v1 - mx);
            float e2 = __expf(v2 - mx);
            float e3 = __expf(v3 - mx);
            float e4 = (lane < 16) ? __expf(v4 - mx) : 0.0f;
            row[lane]       = e0;
            row[lane + 32]  = e1;
            row[lane + 64]  = e2;
            row[lane + 96]  = e3;
            if (lane < 16) row[lane + 128] = e4;
            float s = (e0 + e1) + (e2 + e3) + e4;
#pragma unroll
            for (int off = 16; off > 0; off >>= 1)
                s += __shfl_xor_sync(0xffffffffu, s, off);
            if (lane == 0) rsum[r] = 1.0f / s;
        }
    }
    __syncthreads();

    // Phase 4: O = P v. 16x16 threads, 9 rows x 2 cols per thread,
    // float4 P reads (warp-broadcast), float2 V reads.
    {
        const int tx = tid & 15;   // d pair: d = 2*tx
        const int ty = tid >> 4;   // rows ty*9 .. ty*9+8
        float acc[9][2];
#pragma unroll
        for (int i = 0; i < 9; i++) { acc[i][0] = 0.0f; acc[i][1] = 0.0f; }

        for (int mc = 0; mc < NTOK; mc += 4) {
            float2 v0 = *(float2*)&vS[(mc + 0) * HD + 2 * tx];
            float2 v1 = *(float2*)&vS[(mc + 1) * HD + 2 * tx];
            float2 v2 = *(float2*)&vS[(mc + 2) * HD + 2 * tx];
            float2 v3 = *(float2*)&vS[(mc + 3) * HD + 2 * tx];
#pragma unroll
            for (int i = 0; i < 9; i++) {
                float4 p = *(float4*)&S[(ty * 9 + i) * S_PITCH + mc];
                acc[i][0] += p.x * v0.x + p.y * v1.x + p.z * v2.x + p.w * v3.x;
                acc[i][1] += p.x * v0.y + p.y * v1.y + p.z * v2.y + p.w * v3.y;
            }
        }
        float* ob = out + (size_t)bw * NTOK * DIM + h * HD + 2 * tx;
#pragma unroll
        for (int i = 0; i < 9; i++) {
            int n = ty * 9 + i;
            float r = rsum[n];
            float2 o; o.x = acc[i][0] * r; o.y = acc[i][1] * r;
            *(float2*)(ob + (size_t)n * DIM) = o;
        }
    }
}

// ---------------------------------------------------------------------------
extern "C" void kernel_launch(void* const* d_in, const int* in_sizes, int n_in,
                              void* d_out, int out_size)
{
    const float* x          = (const float*)d_in[0];
    const float* mask       = (const float*)d_in[1];
    const float* qkv_w      = (const float*)d_in[2];
    const float* qkv_b      = (const float*)d_in[3];
    const float* proj_w     = (const float*)d_in[4];
    const float* proj_b     = (const float*)d_in[5];
    const float* bias_table = (const float*)d_in[6];
    float* out = (float*)d_out;

    float *qkv_s, *att_s, *biasT_s;
    cudaGetSymbolAddress((void**)&qkv_s, g_qkv);
    cudaGetSymbolAddress((void**)&att_s, g_att);
    cudaGetSymbolAddress((void**)&biasT_s, g_biasT);

    cudaFuncSetAttribute(attn_kernel,
                         cudaFuncAttributeMaxDynamicSharedMemorySize,
                         ATT_SMEM_BYTES);

    // 0) Bias table pre-transpose (tiny)
    bias_transpose_kernel<<<NBIAS, NW * NH>>>(bias_table, biasT_s);

    // 1) QKV projection: (138240 x 192) @ (192 x 576) + b
    gemm_bias_kernel<<<dim3(QKV_N / BN, MROWS / BM), 128>>>(
        x, qkv_w, qkv_b, qkv_s, MROWS, QKV_N, DIM);

    // 2) Fused windowed attention per (w, b, h)
    attn_kernel<<<dim3(NW, B_LON, NH), 256, ATT_SMEM_BYTES>>>(
        qkv_s, mask, biasT_s, att_s);

    // 3) Output projection: (138240 x 192) @ (192 x 192) + b
    gemm_bias_kernel<<<dim3(DIM / BN, MROWS / BM), 128>>>(
        att_s, proj_w, proj_b, out, MROWS, DIM, DIM);
}

// round 6
// speedup vs baseline: 1.3530x; 1.1000x over previous
#include <cuda_runtime.h>
#include <cuda_bf16.h>
#include <cstdint>

// Problem constants
#define B_LON   15
#define NW      64
#define NTOK    144
#define NPAD    160            // padded score columns (warp-clean tiling)
#define DIM     192
#define NH      6
#define HD      32
#define MROWS   (B_LON * NW * NTOK)   // 138240
#define QKV_N   (3 * DIM)             // 576
#define NBIAS   3312
#define RB      72             // rows per attention CTA (half a window)

// Scratch (allocation-free rule: __device__ globals)
__device__ float g_qkv[(size_t)B_LON * NW * NTOK * QKV_N];   // 318 MB
__device__ float g_att[(size_t)B_LON * NW * NTOK * DIM];     // 106 MB
__device__ float g_biasT[(size_t)NW * NH * NBIAS];           // 5 MB: [w*NH+h][idx]

// ---------------------------------------------------------------------------
// Bias table transpose: g_biasT[wh][idx] = bias_table[idx][wh]
// ---------------------------------------------------------------------------
__global__ void bias_transpose_kernel(const float* __restrict__ bias_table,
                                      float* __restrict__ biasT)
{
    int idx = blockIdx.x;          // 0..3311
    int wh  = threadIdx.x;         // 0..383
    biasT[(size_t)wh * NBIAS + idx] = bias_table[(size_t)idx * (NW * NH) + wh];
}

// ---------------------------------------------------------------------------
// fp32 GEMM + bias: C[M,N] = A[M,K] * B[K,N] + bias[N]
// BM=128, BN=64, BK=16, 128 threads, 8x8 per-thread tile, float4 smem reads,
// register-prefetch of the next K tile.
// ---------------------------------------------------------------------------
#define BM 128
#define BN 64
#define BK 16
#define A_PITCH 132

__global__ __launch_bounds__(128, 3) void gemm_bias_kernel(
    const float* __restrict__ A, const float* __restrict__ B,
    const float* __restrict__ bias, float* __restrict__ C,
    int M, int N, int K)
{
    __shared__ float As[BK * A_PITCH];   // [k][m]
    __shared__ float Bs[BK * BN];        // [k][n]

    const int tid = threadIdx.x;
    const int tx = tid & 7;
    const int ty = tid >> 3;
    const int m0 = blockIdx.y * BM;
    const int n0 = blockIdx.x * BN;

    const int ar = tid >> 2;
    const int ac = (tid & 3) * 4;
    const float* Ap = A + (size_t)(m0 + ar) * K + ac;
    const int br = tid >> 4;
    const int bc = (tid & 15) * 4;
    const float* Bp = B + (size_t)br * N + n0 + bc;

    float acc[8][8];
#pragma unroll
    for (int i = 0; i < 8; i++)
#pragma unroll
        for (int j = 0; j < 8; j++) acc[i][j] = 0.0f;

    const int T = K / BK;
    float4 pa[4], pb[2];

#pragma unroll
    for (int s = 0; s < 4; s++) pa[s] = *(const float4*)(Ap + (size_t)s * 32 * K);
#pragma unroll
    for (int s = 0; s < 2; s++) pb[s] = *(const float4*)(Bp + (size_t)s * 8 * N);
#pragma unroll
    for (int s = 0; s < 4; s++) {
        int r = s * 32 + ar;
        As[(ac + 0) * A_PITCH + r] = pa[s].x;
        As[(ac + 1) * A_PITCH + r] = pa[s].y;
        As[(ac + 2) * A_PITCH + r] = pa[s].z;
        As[(ac + 3) * A_PITCH + r] = pa[s].w;
    }
#pragma unroll
    for (int s = 0; s < 2; s++)
        *(float4*)&Bs[(s * 8 + br) * BN + bc] = pb[s];

    for (int t = 0; t < T; t++) {
        __syncthreads();

        if (t + 1 < T) {
            const float* Ap2 = Ap + (t + 1) * BK;
            const float* Bp2 = Bp + (size_t)(t + 1) * BK * N;
#pragma unroll
            for (int s = 0; s < 4; s++) pa[s] = *(const float4*)(Ap2 + (size_t)s * 32 * K);
#pragma unroll
            for (int s = 0; s < 2; s++) pb[s] = *(const float4*)(Bp2 + (size_t)s * 8 * N);
        }

#pragma unroll
        for (int kk = 0; kk < BK; kk++) {
            float4 a0 = *(float4*)&As[kk * A_PITCH + ty * 4];
            float4 a1 = *(float4*)&As[kk * A_PITCH + 64 + ty * 4];
            float4 b0 = *(float4*)&Bs[kk * BN + tx * 4];
            float4 b1 = *(float4*)&Bs[kk * BN + 32 + tx * 4];
            float a[8] = {a0.x, a0.y, a0.z, a0.w, a1.x, a1.y, a1.z, a1.w};
            float b[8] = {b0.x, b0.y, b0.z, b0.w, b1.x, b1.y, b1.z, b1.w};
#pragma unroll
            for (int i = 0; i < 8; i++)
#pragma unroll
                for (int j = 0; j < 8; j++) acc[i][j] += a[i] * b[j];
        }

        __syncthreads();

        if (t + 1 < T) {
#pragma unroll
            for (int s = 0; s < 4; s++) {
                int r = s * 32 + ar;
                As[(ac + 0) * A_PITCH + r] = pa[s].x;
                As[(ac + 1) * A_PITCH + r] = pa[s].y;
                As[(ac + 2) * A_PITCH + r] = pa[s].z;
                As[(ac + 3) * A_PITCH + r] = pa[s].w;
            }
#pragma unroll
            for (int s = 0; s < 2; s++)
                *(float4*)&Bs[(s * 8 + br) * BN + bc] = pb[s];
        }
    }

    float4 bv0 = *(const float4*)(bias + n0 + tx * 4);
    float4 bv1 = *(const float4*)(bias + n0 + 32 + tx * 4);
#pragma unroll
    for (int i = 0; i < 8; i++) {
        int row = m0 + ((i < 4) ? (ty * 4 + i) : (64 + ty * 4 + i - 4));
        float4 o0, o1;
        o0.x = acc[i][0] + bv0.x; o0.y = acc[i][1] + bv0.y;
        o0.z = acc[i][2] + bv0.z; o0.w = acc[i][3] + bv0.w;
        o1.x = acc[i][4] + bv1.x; o1.y = acc[i][5] + bv1.y;
        o1.z = acc[i][6] + bv1.z; o1.w = acc[i][7] + bv1.w;
        *(float4*)(C + (size_t)row * N + n0 + tx * 4) = o0;
        *(float4*)(C + (size_t)row * N + n0 + 32 + tx * 4) = o1;
    }
}

// ---------------------------------------------------------------------------
// Fused attention, half-window row blocks: CTA = (b, w, h, rb) where rb
// selects rows [rb*72, rb*72+72). Columns padded to 160 for warp-clean tiles.
// Earth position index: idx = f(n) + g(m):
//   f = 828*zi + 23*hi + wi ;  g = 1656*zj + 138*hj - wj + 11
// smem: 109.6 KB -> 2 CTAs/SM (16 warps).
// ---------------------------------------------------------------------------
#define QT_PITCH 76
#define KT_PITCH 164
#define S_PITCH  160
#define SM_QT    0
#define SM_KT    (SM_QT + 32 * QT_PITCH)            // 2432
#define SM_VS    (SM_KT + 32 * KT_PITCH)            // +5248
#define SM_S     (SM_VS + NTOK * HD)                // +4608
#define SM_RSUM  (SM_S + RB * S_PITCH)              // +11520
#define SM_BIAS  (SM_RSUM + RB)                     // +72
#define SM_END_F (SM_BIAS + NBIAS)                  // +3312 = 27192 floats
#define ATT_SMEM_BYTES (SM_END_F * 4 + (RB + NTOK) * 4)

__global__ __launch_bounds__(256, 2) void attn_kernel(
    const float* __restrict__ qkv, const float* __restrict__ mask,
    const float* __restrict__ biasT, float* __restrict__ out)
{
    extern __shared__ float sm[];
    float* qT    = sm + SM_QT;     // [32][76]   scaled q^T, local rows
    float* kT    = sm + SM_KT;     // [32][164]  k^T, cols 144..159 zero
    float* vS    = sm + SM_VS;     // [144][32]
    float* S     = sm + SM_S;      // [72][160]
    float* rsum  = sm + SM_RSUM;   // [72]
    float* sbias = sm + SM_BIAS;   // [3312]
    int*   fI    = (int*)(sm + SM_END_F);   // [72]  local rows
    int*   gI    = fI + RB;                 // [144]

    const int w = blockIdx.x, b = blockIdx.y;
    const int h  = blockIdx.z >> 1;
    const int rb = blockIdx.z & 1;
    const int tid  = threadIdx.x;
    const int lane = tid & 31;
    const int wp   = tid >> 5;          // 8 warps
    const int bw = b * NW + w;
    const int row0 = rb * RB;
    const float* base = qkv + (size_t)bw * NTOK * QKV_N;
    const float scale = 0.17677669529663687f;  // 1/sqrt(32)

    // ---- Stage k^T (all rows), v (all rows), q^T (local 72 rows, scaled)
    for (int idx = tid; idx < NTOK * 8; idx += 256) {
        int n = idx >> 3;
        int d = (idx & 7) * 4;
        const float* p = base + n * QKV_N + h * HD + d;
        float4 k4 = *(const float4*)(p + DIM);
        float4 v4 = *(const float4*)(p + 2 * DIM);
        kT[(d + 0) * KT_PITCH + n] = k4.x;
        kT[(d + 1) * KT_PITCH + n] = k4.y;
        kT[(d + 2) * KT_PITCH + n] = k4.z;
        kT[(d + 3) * KT_PITCH + n] = k4.w;
        *(float4*)(vS + n * HD + d) = v4;
        int nl = n - row0;
        if ((unsigned)nl < RB) {
            float4 q4 = *(const float4*)(p);
            qT[(d + 0) * QT_PITCH + nl] = q4.x * scale;
            qT[(d + 1) * QT_PITCH + nl] = q4.y * scale;
            qT[(d + 2) * QT_PITCH + nl] = q4.z * scale;
            qT[(d + 3) * QT_PITCH + nl] = q4.w * scale;
        }
    }
    // Zero kT pad columns 144..163
    for (int i = tid; i < 32 * 20; i += 256) {
        int d = i / 20, c = 144 + (i % 20);
        kT[d * KT_PITCH + c] = 0.0f;
    }
    // Bias slice (contiguous after pre-transpose)
    {
        const float* bsrc = biasT + (size_t)(w * NH + h) * NBIAS;
        for (int i = tid * 4; i < NBIAS; i += 1024)
            *(float4*)(sbias + i) = *(const float4*)(bsrc + i);
    }
    if (tid < RB) {
        int n = row0 + tid;
        int zi = n / 72, hi = (n / 12) % 6, wi = n % 12;
        fI[tid] = 828 * zi + 23 * hi + wi;
    }
    if (tid < NTOK) {
        int zj = tid / 72, hj = (tid / 12) % 6, wj = tid % 12;
        gI[tid] = 1656 * zj + 138 * hj - wj + 11;
    }
    __syncthreads();

    // ---- Phase 2: S = q.k + bias + mask. Warp wp: rows wp*9..wp*9+8,
    // cols lane+32j (j<5). Pad cols get -1e30.
    {
        float acc[9][5];
#pragma unroll
        for (int i = 0; i < 9; i++)
#pragma unroll
            for (int j = 0; j < 5; j++) acc[i][j] = 0.0f;

#pragma unroll 4
        for (int d = 0; d < HD; d++) {
            float qv[9], kv[5];
#pragma unroll
            for (int i = 0; i < 9; i++) qv[i] = qT[d * QT_PITCH + wp * 9 + i];
#pragma unroll
            for (int j = 0; j < 5; j++) kv[j] = kT[d * KT_PITCH + lane + 32 * j];
#pragma unroll
            for (int i = 0; i < 9; i++)
#pragma unroll
                for (int j = 0; j < 5; j++) acc[i][j] += qv[i] * kv[j];
        }

        const float* mbase = mask + (size_t)bw * NTOK * NTOK;
        int gm[5];
#pragma unroll
        for (int j = 0; j < 5; j++) {
            int m = lane + 32 * j;
            gm[j] = (m < NTOK) ? gI[m] : 0;
        }
#pragma unroll
        for (int i = 0; i < 9; i++) {
            int nl = wp * 9 + i;
            int fn = fI[nl];
            const float* mrow = mbase + (size_t)(row0 + nl) * NTOK;
#pragma unroll
            for (int j = 0; j < 5; j++) {
                int m = lane + 32 * j;
                float val = (m < NTOK)
                    ? acc[i][j] + sbias[fn + gm[j]] + mrow[m]
                    : -1e30f;
                S[nl * S_PITCH + m] = val;
            }
        }
    }
    __syncthreads();

    // ---- Phase 3: softmax, warp wp owns rows wp*9..wp*9+8.
    {
#pragma unroll
        for (int i = 0; i < 9; i++) {
            float* row = S + (wp * 9 + i) * S_PITCH;
            float v0 = row[lane];
            float v1 = row[lane + 32];
            float v2 = row[lane + 64];
            float v3 = row[lane + 96];
            float v4 = row[lane + 128];          // pad cols hold -1e30
            float mx = fmaxf(fmaxf(fmaxf(v0, v1), fmaxf(v2, v3)), v4);
#pragma unroll
            for (int off = 16; off > 0; off >>= 1)
                mx = fmaxf(mx, __shfl_xor_sync(0xffffffffu, mx, off));
            float e0 = __expf(v0 - mx);
            float e1 = __expf(v1 - mx);
            float e2 = __expf(v2 - mx);
            float e3 = __expf(v3 - mx);
            float e4 = __expf(v4 - mx);          // -> 0 on pad cols
            row[lane]       = e0;
            row[lane + 32]  = e1;
            row[lane + 64]  = e2;
            row[lane + 96]  = e3;
            row[lane + 128] = e4;
            float s = (e0 + e1) + (e2 + e3) + e4;
#pragma unroll
            for (int off = 16; off > 0; off >>= 1)
                s += __shfl_xor_sync(0xffffffffu, s, off);
            if (lane == 0) rsum[wp * 9 + i] = 1.0f / s;
        }
    }
    __syncthreads();

    // ---- Phase 4: O = P v. Warp wp: rows wp*9..wp*9+8, lane = d.
    {
        float acc[9];
#pragma unroll
        for (int i = 0; i < 9; i++) acc[i] = 0.0f;

        for (int mc = 0; mc < NTOK; mc += 4) {
            float v0 = vS[(mc + 0) * HD + lane];
            float v1 = vS[(mc + 1) * HD + lane];
            float v2 = vS[(mc + 2) * HD + lane];
            float v3 = vS[(mc + 3) * HD + lane];
#pragma unroll
            for (int i = 0; i < 9; i++) {
                float4 p = *(float4*)&S[(wp * 9 + i) * S_PITCH + mc];
                acc[i] += p.x * v0 + p.y * v1 + p.z * v2 + p.w * v3;
            }
        }
        float* ob = out + (size_t)bw * NTOK * DIM + h * HD + lane;
#pragma unroll
        for (int i = 0; i < 9; i++) {
            int nl = wp * 9 + i;
            ob[(size_t)(row0 + nl) * DIM] = acc[i] * rsum[nl];
        }
    }
}

// ---------------------------------------------------------------------------
extern "C" void kernel_launch(void* const* d_in, const int* in_sizes, int n_in,
                              void* d_out, int out_size)
{
    const float* x          = (const float*)d_in[0];
    const float* mask       = (const float*)d_in[1];
    const float* qkv_w      = (const float*)d_in[2];
    const float* qkv_b      = (const float*)d_in[3];
    const float* proj_w     = (const float*)d_in[4];
    const float* proj_b     = (const float*)d_in[5];
    const float* bias_table = (const float*)d_in[6];
    float* out = (float*)d_out;

    float *qkv_s, *att_s, *biasT_s;
    cudaGetSymbolAddress((void**)&qkv_s, g_qkv);
    cudaGetSymbolAddress((void**)&att_s, g_att);
    cudaGetSymbolAddress((void**)&biasT_s, g_biasT);

    cudaFuncSetAttribute(attn_kernel,
                         cudaFuncAttributeMaxDynamicSharedMemorySize,
                         ATT_SMEM_BYTES);

    // 0) Bias table pre-transpose (tiny)
    bias_transpose_kernel<<<NBIAS, NW * NH>>>(bias_table, biasT_s);

    // 1) QKV projection: (138240 x 192) @ (192 x 576) + b
    gemm_bias_kernel<<<dim3(QKV_N / BN, MROWS / BM), 128>>>(
        x, qkv_w, qkv_b, qkv_s, MROWS, QKV_N, DIM);

    // 2) Fused windowed attention per (w, b, h, row-half)
    attn_kernel<<<dim3(NW, B_LON, NH * 2), 256, ATT_SMEM_BYTES>>>(
        qkv_s, mask, biasT_s, att_s);

    // 3) Output projection: (138240 x 192) @ (192 x 192) + b
    gemm_bias_kernel<<<dim3(DIM / BN, MROWS / BM), 128>>>(
        att_s, proj_w, proj_b, out, MROWS, DIM, DIM);
}

// round 7
// speedup vs baseline: 1.6204x; 1.1976x over previous
#include <cuda_runtime.h>
#include <cuda_bf16.h>
#include <cstdint>

// Problem constants
#define B_LON   15
#define NW      64
#define NTOK    144
#define DIM     192
#define NH      6
#define HD      32
#define MROWS   (B_LON * NW * NTOK)   // 138240
#define QKV_N   (3 * DIM)             // 576
#define NBIAS   3312
#define RB      72             // rows per attention CTA (half a window)

// Scratch (allocation-free rule: __device__ globals)
__device__ float g_qkv[(size_t)B_LON * NW * NTOK * QKV_N];   // 318 MB
__device__ float g_att[(size_t)B_LON * NW * NTOK * DIM];     // 106 MB
__device__ float g_biasT[(size_t)NW * NH * NBIAS];           // 5 MB: [w*NH+h][idx]

// ---------------------------------------------------------------------------
__global__ void bias_transpose_kernel(const float* __restrict__ bias_table,
                                      float* __restrict__ biasT)
{
    int idx = blockIdx.x;          // 0..3311
    int wh  = threadIdx.x;         // 0..383
    biasT[(size_t)wh * NBIAS + idx] = bias_table[(size_t)idx * (NW * NH) + wh];
}

// ---------------------------------------------------------------------------
// tf32 tensor-core GEMM + bias: C[M,N] = A[M,K] * B[K,N] + bias[N]
// BM=128, BN=64, BK=16, 256 threads = 8 warps (4M x 2N), warp tile 32x32.
// mma.sync.aligned.m16n8k8.row.col.f32.tf32.tf32.f32
// A smem [m][k] pitch 20 (conflict-free frag LDS); B smem [k][n] pitch 72.
// ---------------------------------------------------------------------------
#define BM 128
#define BN 64
#define BK 16
#define AP 20     // A smem pitch (floats)
#define BP 72     // B smem pitch (floats)

__device__ __forceinline__ uint32_t f2tf32(float f) {
    uint32_t u;
    asm("cvt.rna.tf32.f32 %0, %1;" : "=r"(u) : "f"(f));
    return u;
}

__device__ __forceinline__ void mma_tf32(float* c, const uint32_t* a,
                                         const uint32_t* b) {
    asm volatile(
        "mma.sync.aligned.m16n8k8.row.col.f32.tf32.tf32.f32 "
        "{%0,%1,%2,%3}, {%4,%5,%6,%7}, {%8,%9}, {%0,%1,%2,%3};"
        : "+f"(c[0]), "+f"(c[1]), "+f"(c[2]), "+f"(c[3])
        : "r"(a[0]), "r"(a[1]), "r"(a[2]), "r"(a[3]),
          "r"(b[0]), "r"(b[1]));
}

__global__ __launch_bounds__(256, 2) void gemm_tf32_kernel(
    const float* __restrict__ A, const float* __restrict__ B,
    const float* __restrict__ bias, float* __restrict__ C,
    int M, int N, int K)
{
    __shared__ uint32_t As[BM * AP];   // [m][k], tf32 bits
    __shared__ uint32_t Bs[BK * BP];   // [k][n], tf32 bits

    const int tid  = threadIdx.x;
    const int lane = tid & 31;
    const int wid  = tid >> 5;        // 8 warps
    const int wm   = wid & 3;         // warp M index (4)
    const int wn   = wid >> 2;        // warp N index (2)
    const int grp  = lane >> 2;       // 0..7
    const int tig  = lane & 3;        // 0..3

    const int m0 = blockIdx.y * BM;
    const int n0 = blockIdx.x * BN;

    // Staging mappings
    const int ar = tid >> 2;          // 0..63 (s adds 64)
    const int ac = (tid & 3) * 4;     // 0,4,8,12
    const float* Ap0 = A + (size_t)(m0 + ar) * K + ac;
    const int bk = tid >> 4;          // 0..15
    const int bn = (tid & 15) * 4;    // 0..60
    const float* Bp0 = B + (size_t)bk * N + n0 + bn;

    float acc[2][4][4];
#pragma unroll
    for (int mi = 0; mi < 2; mi++)
#pragma unroll
        for (int ni = 0; ni < 4; ni++)
#pragma unroll
            for (int r = 0; r < 4; r++) acc[mi][ni][r] = 0.0f;

    const int T = K / BK;   // 12
    float4 pa[2], pb;

    // Prologue: stage tile 0
#pragma unroll
    for (int s = 0; s < 2; s++) pa[s] = *(const float4*)(Ap0 + (size_t)s * 64 * K);
    pb = *(const float4*)(Bp0);
#pragma unroll
    for (int s = 0; s < 2; s++) {
        int r = s * 64 + ar;
        uint4 u;
        u.x = f2tf32(pa[s].x); u.y = f2tf32(pa[s].y);
        u.z = f2tf32(pa[s].z); u.w = f2tf32(pa[s].w);
        *(uint4*)&As[r * AP + ac] = u;
    }
    {
        uint4 u;
        u.x = f2tf32(pb.x); u.y = f2tf32(pb.y);
        u.z = f2tf32(pb.z); u.w = f2tf32(pb.w);
        *(uint4*)&Bs[bk * BP + bn] = u;
    }

    for (int t = 0; t < T; t++) {
        __syncthreads();   // stage t visible

        if (t + 1 < T) {   // prefetch stage t+1 into registers
            const float* Ap2 = Ap0 + (t + 1) * BK;
            const float* Bp2 = Bp0 + (size_t)(t + 1) * BK * N;
#pragma unroll
            for (int s = 0; s < 2; s++) pa[s] = *(const float4*)(Ap2 + (size_t)s * 64 * K);
            pb = *(const float4*)(Bp2);
        }

        // Two k-chunks of 8
#pragma unroll
        for (int kc = 0; kc < BK; kc += 8) {
            uint32_t af[2][4], bf[4][2];
#pragma unroll
            for (int mi = 0; mi < 2; mi++) {
                int mbase = wm * 32 + mi * 16 + grp;
                af[mi][0] = As[(mbase)     * AP + kc + tig];
                af[mi][1] = As[(mbase + 8) * AP + kc + tig];
                af[mi][2] = As[(mbase)     * AP + kc + tig + 4];
                af[mi][3] = As[(mbase + 8) * AP + kc + tig + 4];
            }
#pragma unroll
            for (int ni = 0; ni < 4; ni++) {
                int nbase = wn * 32 + ni * 8 + grp;
                bf[ni][0] = Bs[(kc + tig)     * BP + nbase];
                bf[ni][1] = Bs[(kc + tig + 4) * BP + nbase];
            }
#pragma unroll
            for (int mi = 0; mi < 2; mi++)
#pragma unroll
                for (int ni = 0; ni < 4; ni++)
                    mma_tf32(acc[mi][ni], af[mi], bf[ni]);
        }

        __syncthreads();   // done reading stage t

        if (t + 1 < T) {   // store stage t+1
#pragma unroll
            for (int s = 0; s < 2; s++) {
                int r = s * 64 + ar;
                uint4 u;
                u.x = f2tf32(pa[s].x); u.y = f2tf32(pa[s].y);
                u.z = f2tf32(pa[s].z); u.w = f2tf32(pa[s].w);
                *(uint4*)&As[r * AP + ac] = u;
            }
            uint4 u;
            u.x = f2tf32(pb.x); u.y = f2tf32(pb.y);
            u.z = f2tf32(pb.z); u.w = f2tf32(pb.w);
            *(uint4*)&Bs[bk * BP + bn] = u;
        }
    }

    // Epilogue: c0,c1 at (row, 2*tig..+1); c2,c3 at (row+8, same cols)
#pragma unroll
    for (int mi = 0; mi < 2; mi++) {
        int row = m0 + wm * 32 + mi * 16 + grp;
#pragma unroll
        for (int ni = 0; ni < 4; ni++) {
            int col = n0 + wn * 32 + ni * 8 + 2 * tig;
            float2 bv = *(const float2*)(bias + col);
            float2 o0, o1;
            o0.x = acc[mi][ni][0] + bv.x;
            o0.y = acc[mi][ni][1] + bv.y;
            o1.x = acc[mi][ni][2] + bv.x;
            o1.y = acc[mi][ni][3] + bv.y;
            *(float2*)(C + (size_t)row * N + col)       = o0;
            *(float2*)(C + (size_t)(row + 8) * N + col) = o1;
        }
    }
}

// ---------------------------------------------------------------------------
// Fused attention, half-window row blocks (unchanged from previous round).
// idx = f(n) + g(m): f = 828*zi + 23*hi + wi ; g = 1656*zj + 138*hj - wj + 11
// ---------------------------------------------------------------------------
#define QT_PITCH 76
#define KT_PITCH 164
#define S_PITCH  160
#define SM_QT    0
#define SM_KT    (SM_QT + 32 * QT_PITCH)
#define SM_VS    (SM_KT + 32 * KT_PITCH)
#define SM_S     (SM_VS + NTOK * HD)
#define SM_RSUM  (SM_S + RB * S_PITCH)
#define SM_BIAS  (SM_RSUM + RB)
#define SM_END_F (SM_BIAS + NBIAS)
#define ATT_SMEM_BYTES (SM_END_F * 4 + (RB + NTOK) * 4)

__global__ __launch_bounds__(256, 2) void attn_kernel(
    const float* __restrict__ qkv, const float* __restrict__ mask,
    const float* __restrict__ biasT, float* __restrict__ out)
{
    extern __shared__ float sm[];
    float* qT    = sm + SM_QT;     // [32][76]
    float* kT    = sm + SM_KT;     // [32][164]
    float* vS    = sm + SM_VS;     // [144][32]
    float* S     = sm + SM_S;      // [72][160]
    float* rsum  = sm + SM_RSUM;   // [72]
    float* sbias = sm + SM_BIAS;   // [3312]
    int*   fI    = (int*)(sm + SM_END_F);   // [72]
    int*   gI    = fI + RB;                 // [144]

    const int w = blockIdx.x, b = blockIdx.y;
    const int h  = blockIdx.z >> 1;
    const int rb = blockIdx.z & 1;
    const int tid  = threadIdx.x;
    const int lane = tid & 31;
    const int wp   = tid >> 5;
    const int bw = b * NW + w;
    const int row0 = rb * RB;
    const float* base = qkv + (size_t)bw * NTOK * QKV_N;
    const float scale = 0.17677669529663687f;

    for (int idx = tid; idx < NTOK * 8; idx += 256) {
        int n = idx >> 3;
        int d = (idx & 7) * 4;
        const float* p = base + n * QKV_N + h * HD + d;
        float4 k4 = *(const float4*)(p + DIM);
        float4 v4 = *(const float4*)(p + 2 * DIM);
        kT[(d + 0) * KT_PITCH + n] = k4.x;
        kT[(d + 1) * KT_PITCH + n] = k4.y;
        kT[(d + 2) * KT_PITCH + n] = k4.z;
        kT[(d + 3) * KT_PITCH + n] = k4.w;
        *(float4*)(vS + n * HD + d) = v4;
        int nl = n - row0;
        if ((unsigned)nl < RB) {
            float4 q4 = *(const float4*)(p);
            qT[(d + 0) * QT_PITCH + nl] = q4.x * scale;
            qT[(d + 1) * QT_PITCH + nl] = q4.y * scale;
            qT[(d + 2) * QT_PITCH + nl] = q4.z * scale;
            qT[(d + 3) * QT_PITCH + nl] = q4.w * scale;
        }
    }
    for (int i = tid; i < 32 * 20; i += 256) {
        int d = i / 20, c = 144 + (i % 20);
        kT[d * KT_PITCH + c] = 0.0f;
    }
    {
        const float* bsrc = biasT + (size_t)(w * NH + h) * NBIAS;
        for (int i = tid * 4; i < NBIAS; i += 1024)
            *(float4*)(sbias + i) = *(const float4*)(bsrc + i);
    }
    if (tid < RB) {
        int n = row0 + tid;
        int zi = n / 72, hi = (n / 12) % 6, wi = n % 12;
        fI[tid] = 828 * zi + 23 * hi + wi;
    }
    if (tid < NTOK) {
        int zj = tid / 72, hj = (tid / 12) % 6, wj = tid % 12;
        gI[tid] = 1656 * zj + 138 * hj - wj + 11;
    }
    __syncthreads();

    {
        float acc[9][5];
#pragma unroll
        for (int i = 0; i < 9; i++)
#pragma unroll
            for (int j = 0; j < 5; j++) acc[i][j] = 0.0f;

#pragma unroll 4
        for (int d = 0; d < HD; d++) {
            float qv[9], kv[5];
#pragma unroll
            for (int i = 0; i < 9; i++) qv[i] = qT[d * QT_PITCH + wp * 9 + i];
#pragma unroll
            for (int j = 0; j < 5; j++) kv[j] = kT[d * KT_PITCH + lane + 32 * j];
#pragma unroll
            for (int i = 0; i < 9; i++)
#pragma unroll
                for (int j = 0; j < 5; j++) acc[i][j] += qv[i] * kv[j];
        }

        const float* mbase = mask + (size_t)bw * NTOK * NTOK;
        int gm[5];
#pragma unroll
        for (int j = 0; j < 5; j++) {
            int m = lane + 32 * j;
            gm[j] = (m < NTOK) ? gI[m] : 0;
        }
#pragma unroll
        for (int i = 0; i < 9; i++) {
            int nl = wp * 9 + i;
            int fn = fI[nl];
            const float* mrow = mbase + (size_t)(row0 + nl) * NTOK;
#pragma unroll
            for (int j = 0; j < 5; j++) {
                int m = lane + 32 * j;
                float val = (m < NTOK)
                    ? acc[i][j] + sbias[fn + gm[j]] + mrow[m]
                    : -1e30f;
                S[nl * S_PITCH + m] = val;
            }
        }
    }
    __syncthreads();

    {
#pragma unroll
        for (int i = 0; i < 9; i++) {
            float* row = S + (wp * 9 + i) * S_PITCH;
            float v0 = row[lane];
            float v1 = row[lane + 32];
            float v2 = row[lane + 64];
            float v3 = row[lane + 96];
            float v4 = row[lane + 128];
            float mx = fmaxf(fmaxf(fmaxf(v0, v1), fmaxf(v2, v3)), v4);
#pragma unroll
            for (int off = 16; off > 0; off >>= 1)
                mx = fmaxf(mx, __shfl_xor_sync(0xffffffffu, mx, off));
            float e0 = __expf(v0 - mx);
            float e1 = __expf(v1 - mx);
            float e2 = __expf(v2 - mx);
            float e3 = __expf(v3 - mx);
            float e4 = __expf(v4 - mx);
            row[lane]       = e0;
            row[lane + 32]  = e1;
            row[lane + 64]  = e2;
            row[lane + 96]  = e3;
            row[lane + 128] = e4;
            float s = (e0 + e1) + (e2 + e3) + e4;
#pragma unroll
            for (int off = 16; off > 0; off >>= 1)
                s += __shfl_xor_sync(0xffffffffu, s, off);
            if (lane == 0) rsum[wp * 9 + i] = 1.0f / s;
        }
    }
    __syncthreads();

    {
        float acc[9];
#pragma unroll
        for (int i = 0; i < 9; i++) acc[i] = 0.0f;

        for (int mc = 0; mc < NTOK; mc += 4) {
            float v0 = vS[(mc + 0) * HD + lane];
            float v1 = vS[(mc + 1) * HD + lane];
            float v2 = vS[(mc + 2) * HD + lane];
            float v3 = vS[(mc + 3) * HD + lane];
#pragma unroll
            for (int i = 0; i < 9; i++) {
                float4 p = *(float4*)&S[(wp * 9 + i) * S_PITCH + mc];
                acc[i] += p.x * v0 + p.y * v1 + p.z * v2 + p.w * v3;
            }
        }
        float* ob = out + (size_t)bw * NTOK * DIM + h * HD + lane;
#pragma unroll
        for (int i = 0; i < 9; i++) {
            int nl = wp * 9 + i;
            ob[(size_t)(row0 + nl) * DIM] = acc[i] * rsum[nl];
        }
    }
}

// ---------------------------------------------------------------------------
extern "C" void kernel_launch(void* const* d_in, const int* in_sizes, int n_in,
                              void* d_out, int out_size)
{
    const float* x          = (const float*)d_in[0];
    const float* mask       = (const float*)d_in[1];
    const float* qkv_w      = (const float*)d_in[2];
    const float* qkv_b      = (const float*)d_in[3];
    const float* proj_w     = (const float*)d_in[4];
    const float* proj_b     = (const float*)d_in[5];
    const float* bias_table = (const float*)d_in[6];
    float* out = (float*)d_out;

    float *qkv_s, *att_s, *biasT_s;
    cudaGetSymbolAddress((void**)&qkv_s, g_qkv);
    cudaGetSymbolAddress((void**)&att_s, g_att);
    cudaGetSymbolAddress((void**)&biasT_s, g_biasT);

    cudaFuncSetAttribute(attn_kernel,
                         cudaFuncAttributeMaxDynamicSharedMemorySize,
                         ATT_SMEM_BYTES);

    // 0) Bias table pre-transpose (tiny)
    bias_transpose_kernel<<<NBIAS, NW * NH>>>(bias_table, biasT_s);

    // 1) QKV projection: (138240 x 192) @ (192 x 576) + b   [tf32 tensor]
    gemm_tf32_kernel<<<dim3(QKV_N / BN, MROWS / BM), 256>>>(
        x, qkv_w, qkv_b, qkv_s, MROWS, QKV_N, DIM);

    // 2) Fused windowed attention per (w, b, h, row-half)
    attn_kernel<<<dim3(NW, B_LON, NH * 2), 256, ATT_SMEM_BYTES>>>(
        qkv_s, mask, biasT_s, att_s);

    // 3) Output projection: (138240 x 192) @ (192 x 192) + b   [tf32 tensor]
    gemm_tf32_kernel<<<dim3(DIM / BN, MROWS / BM), 256>>>(
        att_s, proj_w, proj_b, out, MROWS, DIM, DIM);
}

// round 8
// speedup vs baseline: 1.7029x; 1.0509x over previous
#include <cuda_runtime.h>
#include <cuda_bf16.h>
#include <cstdint>

// Problem constants
#define B_LON   15
#define NW      64
#define NTOK    144
#define DIM     192
#define NH      6
#define HD      32
#define MROWS   (B_LON * NW * NTOK)   // 138240
#define QKV_N   (3 * DIM)             // 576
#define NBIAS   3312
#define RB      72             // rows per attention CTA (half a window)

// Scratch (allocation-free rule: __device__ globals)
__device__ float g_qkv[(size_t)B_LON * NW * NTOK * QKV_N];   // 318 MB
__device__ float g_att[(size_t)B_LON * NW * NTOK * DIM];     // 106 MB
__device__ float g_biasT[(size_t)NW * NH * NBIAS];           // 5 MB: [w*NH+h][idx]

// ---------------------------------------------------------------------------
__global__ void bias_transpose_kernel(const float* __restrict__ bias_table,
                                      float* __restrict__ biasT)
{
    int idx = blockIdx.x;          // 0..3311
    int wh  = threadIdx.x;         // 0..383
    biasT[(size_t)wh * NBIAS + idx] = bias_table[(size_t)idx * (NW * NH) + wh];
}

// ---------------------------------------------------------------------------
// tf32 helpers (fragment mapping validated in round-6 GEMM)
// ---------------------------------------------------------------------------
__device__ __forceinline__ uint32_t f2tf32(float f) {
    uint32_t u;
    asm("cvt.rna.tf32.f32 %0, %1;" : "=r"(u) : "f"(f));
    return u;
}

__device__ __forceinline__ void mma_tf32(float* c, const uint32_t* a,
                                         const uint32_t* b) {
    asm volatile(
        "mma.sync.aligned.m16n8k8.row.col.f32.tf32.tf32.f32 "
        "{%0,%1,%2,%3}, {%4,%5,%6,%7}, {%8,%9}, {%0,%1,%2,%3};"
        : "+f"(c[0]), "+f"(c[1]), "+f"(c[2]), "+f"(c[3])
        : "r"(a[0]), "r"(a[1]), "r"(a[2]), "r"(a[3]),
          "r"(b[0]), "r"(b[1]));
}

// ---------------------------------------------------------------------------
// tf32 tensor-core GEMM + bias (unchanged from round 6)
// ---------------------------------------------------------------------------
#define BM 128
#define BN 64
#define BK 16
#define AP 20
#define BP 72

__global__ __launch_bounds__(256, 2) void gemm_tf32_kernel(
    const float* __restrict__ A, const float* __restrict__ B,
    const float* __restrict__ bias, float* __restrict__ C,
    int M, int N, int K)
{
    __shared__ uint32_t As[BM * AP];
    __shared__ uint32_t Bs[BK * BP];

    const int tid  = threadIdx.x;
    const int lane = tid & 31;
    const int wid  = tid >> 5;
    const int wm   = wid & 3;
    const int wn   = wid >> 2;
    const int grp  = lane >> 2;
    const int tig  = lane & 3;

    const int m0 = blockIdx.y * BM;
    const int n0 = blockIdx.x * BN;

    const int ar = tid >> 2;
    const int ac = (tid & 3) * 4;
    const float* Ap0 = A + (size_t)(m0 + ar) * K + ac;
    const int bk = tid >> 4;
    const int bn = (tid & 15) * 4;
    const float* Bp0 = B + (size_t)bk * N + n0 + bn;

    float acc[2][4][4];
#pragma unroll
    for (int mi = 0; mi < 2; mi++)
#pragma unroll
        for (int ni = 0; ni < 4; ni++)
#pragma unroll
            for (int r = 0; r < 4; r++) acc[mi][ni][r] = 0.0f;

    const int T = K / BK;
    float4 pa[2], pb;

#pragma unroll
    for (int s = 0; s < 2; s++) pa[s] = *(const float4*)(Ap0 + (size_t)s * 64 * K);
    pb = *(const float4*)(Bp0);
#pragma unroll
    for (int s = 0; s < 2; s++) {
        int r = s * 64 + ar;
        uint4 u;
        u.x = f2tf32(pa[s].x); u.y = f2tf32(pa[s].y);
        u.z = f2tf32(pa[s].z); u.w = f2tf32(pa[s].w);
        *(uint4*)&As[r * AP + ac] = u;
    }
    {
        uint4 u;
        u.x = f2tf32(pb.x); u.y = f2tf32(pb.y);
        u.z = f2tf32(pb.z); u.w = f2tf32(pb.w);
        *(uint4*)&Bs[bk * BP + bn] = u;
    }

    for (int t = 0; t < T; t++) {
        __syncthreads();

        if (t + 1 < T) {
            const float* Ap2 = Ap0 + (t + 1) * BK;
            const float* Bp2 = Bp0 + (size_t)(t + 1) * BK * N;
#pragma unroll
            for (int s = 0; s < 2; s++) pa[s] = *(const float4*)(Ap2 + (size_t)s * 64 * K);
            pb = *(const float4*)(Bp2);
        }

#pragma unroll
        for (int kc = 0; kc < BK; kc += 8) {
            uint32_t af[2][4], bf[4][2];
#pragma unroll
            for (int mi = 0; mi < 2; mi++) {
                int mbase = wm * 32 + mi * 16 + grp;
                af[mi][0] = As[(mbase)     * AP + kc + tig];
                af[mi][1] = As[(mbase + 8) * AP + kc + tig];
                af[mi][2] = As[(mbase)     * AP + kc + tig + 4];
                af[mi][3] = As[(mbase + 8) * AP + kc + tig + 4];
            }
#pragma unroll
            for (int ni = 0; ni < 4; ni++) {
                int nbase = wn * 32 + ni * 8 + grp;
                bf[ni][0] = Bs[(kc + tig)     * BP + nbase];
                bf[ni][1] = Bs[(kc + tig + 4) * BP + nbase];
            }
#pragma unroll
            for (int mi = 0; mi < 2; mi++)
#pragma unroll
                for (int ni = 0; ni < 4; ni++)
                    mma_tf32(acc[mi][ni], af[mi], bf[ni]);
        }

        __syncthreads();

        if (t + 1 < T) {
#pragma unroll
            for (int s = 0; s < 2; s++) {
                int r = s * 64 + ar;
                uint4 u;
                u.x = f2tf32(pa[s].x); u.y = f2tf32(pa[s].y);
                u.z = f2tf32(pa[s].z); u.w = f2tf32(pa[s].w);
                *(uint4*)&As[r * AP + ac] = u;
            }
            uint4 u;
            u.x = f2tf32(pb.x); u.y = f2tf32(pb.y);
            u.z = f2tf32(pb.z); u.w = f2tf32(pb.w);
            *(uint4*)&Bs[bk * BP + bn] = u;
        }
    }

#pragma unroll
    for (int mi = 0; mi < 2; mi++) {
        int row = m0 + wm * 32 + mi * 16 + grp;
#pragma unroll
        for (int ni = 0; ni < 4; ni++) {
            int col = n0 + wn * 32 + ni * 8 + 2 * tig;
            float2 bv = *(const float2*)(bias + col);
            float2 o0, o1;
            o0.x = acc[mi][ni][0] + bv.x;
            o0.y = acc[mi][ni][1] + bv.y;
            o1.x = acc[mi][ni][2] + bv.x;
            o1.y = acc[mi][ni][3] + bv.y;
            *(float2*)(C + (size_t)row * N + col)       = o0;
            *(float2*)(C + (size_t)(row + 8) * N + col) = o1;
        }
    }
}

// ---------------------------------------------------------------------------
// Fused attention with tensor-core QK^T and PV (tf32 mma.m16n8k8).
// CTA = (b, w, h, rb): rows [rb*72, rb*72+72).
// q,k staged natural row-major tf32 (pitch 36, conflict-free fragments);
// v staged transposed tf32 (pitch 148); S fp32 (pitch 164), mask pre-staged.
// idx = f(n) + g(m): f = 828*zi + 23*hi + wi ; g = 1656*zj + 138*hj - wj + 11
// smem 110.2 KB -> 2 CTAs/SM.
// ---------------------------------------------------------------------------
#define QP 36     // qS pitch (u32)
#define KP 36     // kS pitch (u32)
#define VP 148    // vT pitch (u32)
#define SP 164    // S pitch (f32)

#define SM_QS    0                       // [80][36] u32 (rows 72..79 zero)
#define SM_KS    (SM_QS + 80 * QP)       // [144][36] u32
#define SM_VT    (SM_KS + NTOK * KP)     // [32][148] u32
#define SM_S     (SM_VT + 32 * VP)       // [72][164] f32
#define SM_BIAS  (SM_S + RB * SP)        // [3312] f32 (also phantom S rows)
#define SM_RSUM  (SM_BIAS + NBIAS)       // [72] f32
#define SM_FI    (SM_RSUM + RB)          // [72] int
#define SM_GI    (SM_FI + RB)            // [144] int
#define ATT_SMEM_BYTES ((SM_GI + NTOK) * 4)

__global__ __launch_bounds__(256, 2) void attn_kernel(
    const float* __restrict__ qkv, const float* __restrict__ mask,
    const float* __restrict__ biasT, float* __restrict__ out)
{
    extern __shared__ float sm[];
    uint32_t* qS   = (uint32_t*)sm + SM_QS;
    uint32_t* kS   = (uint32_t*)sm + SM_KS;
    uint32_t* vT   = (uint32_t*)sm + SM_VT;
    float*    S    = sm + SM_S;
    float*    sbias= sm + SM_BIAS;
    float*    rsum = sm + SM_RSUM;
    int*      fI   = (int*)sm + SM_FI;
    int*      gI   = (int*)sm + SM_GI;

    const int w = blockIdx.x, b = blockIdx.y;
    const int h  = blockIdx.z >> 1;
    const int rb = blockIdx.z & 1;
    const int tid  = threadIdx.x;
    const int lane = tid & 31;
    const int wp   = tid >> 5;          // 8 warps
    const int grp  = lane >> 2;         // 0..7
    const int tig  = lane & 3;          // 0..3
    const int bw = b * NW + w;
    const int row0 = rb * RB;
    const float* base = qkv + (size_t)bw * NTOK * QKV_N;
    const float* mbase = mask + (size_t)bw * NTOK * NTOK;
    const float scale = 0.17677669529663687f;  // 1/sqrt(32)

    // ---- Stage q (scaled, tf32, local rows), k (tf32), v^T (tf32)
    for (int idx = tid; idx < NTOK * 8; idx += 256) {
        int n = idx >> 3;
        int d = (idx & 7) * 4;
        const float* p = base + n * QKV_N + h * HD + d;
        float4 k4 = *(const float4*)(p + DIM);
        float4 v4 = *(const float4*)(p + 2 * DIM);
        uint4 ku;
        ku.x = f2tf32(k4.x); ku.y = f2tf32(k4.y);
        ku.z = f2tf32(k4.z); ku.w = f2tf32(k4.w);
        *(uint4*)&kS[n * KP + d] = ku;
        vT[(d + 0) * VP + n] = f2tf32(v4.x);
        vT[(d + 1) * VP + n] = f2tf32(v4.y);
        vT[(d + 2) * VP + n] = f2tf32(v4.z);
        vT[(d + 3) * VP + n] = f2tf32(v4.w);
        int nl = n - row0;
        if ((unsigned)nl < RB) {
            float4 q4 = *(const float4*)(p);
            uint4 qu;
            qu.x = f2tf32(q4.x * scale); qu.y = f2tf32(q4.y * scale);
            qu.z = f2tf32(q4.z * scale); qu.w = f2tf32(q4.w * scale);
            *(uint4*)&qS[nl * QP + d] = qu;
        }
    }
    // Zero qS pad rows 72..79 (contiguous 8*QP words)
    for (int i = tid; i < 8 * QP; i += 256) qS[RB * QP + i] = 0;

    // Pre-stage mask into S cols 0..143 (coalesced)
    for (int idx = tid; idx < RB * 36; idx += 256) {
        int r = idx / 36, c = (idx % 36) * 4;
        *(float4*)&S[r * SP + c] =
            *(const float4*)(mbase + (size_t)(row0 + r) * NTOK + c);
    }
    // Pad cols 144..159 = -1e30
    for (int idx = tid; idx < RB * 4; idx += 256) {
        int r = idx >> 2, c = 144 + (idx & 3) * 4;
        float4 pv = make_float4(-1e30f, -1e30f, -1e30f, -1e30f);
        *(float4*)&S[r * SP + c] = pv;
    }
    // Bias slice
    {
        const float* bsrc = biasT + (size_t)(w * NH + h) * NBIAS;
        for (int i = tid * 4; i < NBIAS; i += 1024)
            *(float4*)(sbias + i) = *(const float4*)(bsrc + i);
    }
    if (tid < RB) {
        int n = row0 + tid;
        int zi = n / 72, hi = (n / 12) % 6, wi = n % 12;
        fI[tid] = 828 * zi + 23 * hi + wi;
    }
    if (tid < NTOK) {
        int zj = tid / 72, hj = (tid / 12) % 6, wj = tid % 12;
        gI[tid] = 1656 * zj + 138 * hj - wj + 11;
    }
    __syncthreads();

    // ---- Phase 2: S = q k^T + bias + mask via mma. 90 tiles (5m x 18n).
    for (int t = wp; t < 90; t += 8) {
        int m0 = (t / 18) * 16;
        int n0 = (t % 18) * 8;
        float c[4] = {0.0f, 0.0f, 0.0f, 0.0f};
#pragma unroll
        for (int kc = 0; kc < HD; kc += 8) {
            uint32_t a[4], bfr[2];
            int ab = (m0 + grp) * QP + kc + tig;
            a[0] = qS[ab];
            a[1] = qS[ab + 8 * QP];
            a[2] = qS[ab + 4];
            a[3] = qS[ab + 8 * QP + 4];
            int bb = (n0 + grp) * KP + kc + tig;
            bfr[0] = kS[bb];
            bfr[1] = kS[bb + 4];
            mma_tf32(c, a, bfr);
        }
        int col = n0 + 2 * tig;
        int g0 = gI[col], g1 = gI[col + 1];
#pragma unroll
        for (int p = 0; p < 2; p++) {
            int r = m0 + grp + p * 8;
            if (r < RB) {
                int f = fI[r];
                float* sr = S + r * SP + col;
                sr[0] = c[2 * p]     + sbias[f + g0] + sr[0];
                sr[1] = c[2 * p + 1] + sbias[f + g1] + sr[1];
            }
        }
    }
    __syncthreads();

    // ---- Phase 3: softmax, warp wp owns rows wp*9..wp*9+8.
    {
#pragma unroll
        for (int i = 0; i < 9; i++) {
            float* row = S + (wp * 9 + i) * SP;
            float v0 = row[lane];
            float v1 = row[lane + 32];
            float v2 = row[lane + 64];
            float v3 = row[lane + 96];
            float v4 = row[lane + 128];          // pad cols hold -1e30
            float mx = fmaxf(fmaxf(fmaxf(v0, v1), fmaxf(v2, v3)), v4);
#pragma unroll
            for (int off = 16; off > 0; off >>= 1)
                mx = fmaxf(mx, __shfl_xor_sync(0xffffffffu, mx, off));
            float e0 = __expf(v0 - mx);
            float e1 = __expf(v1 - mx);
            float e2 = __expf(v2 - mx);
            float e3 = __expf(v3 - mx);
            float e4 = __expf(v4 - mx);
            row[lane]       = e0;
            row[lane + 32]  = e1;
            row[lane + 64]  = e2;
            row[lane + 96]  = e3;
            row[lane + 128] = e4;
            float s = (e0 + e1) + (e2 + e3) + e4;
#pragma unroll
            for (int off = 16; off > 0; off >>= 1)
                s += __shfl_xor_sync(0xffffffffu, s, off);
            if (lane == 0) rsum[wp * 9 + i] = 1.0f / s;
        }
    }
    __syncthreads();

    // ---- Phase 4: O = P v via mma. 20 tiles (5m x 4n), K=144.
    float* ob0 = out + (size_t)bw * NTOK * DIM + h * HD;
    for (int t = wp; t < 20; t += 8) {
        int m0 = (t >> 2) * 16;
        int n0 = (t & 3) * 8;
        float c[4] = {0.0f, 0.0f, 0.0f, 0.0f};
#pragma unroll 6
        for (int kc = 0; kc < NTOK; kc += 8) {
            uint32_t a[4], bfr[2];
            const float* ap = S + (m0 + grp) * SP + kc + tig;
            a[0] = f2tf32(ap[0]);
            a[1] = f2tf32(ap[8 * SP]);
            a[2] = f2tf32(ap[4]);
            a[3] = f2tf32(ap[8 * SP + 4]);
            int bb = (n0 + grp) * VP + kc + tig;
            bfr[0] = vT[bb];
            bfr[1] = vT[bb + 4];
            mma_tf32(c, a, bfr);
        }
        int col = n0 + 2 * tig;
#pragma unroll
        for (int p = 0; p < 2; p++) {
            int r = m0 + grp + p * 8;
            if (r < RB) {
                float rs = rsum[r];
                float2 o;
                o.x = c[2 * p] * rs;
                o.y = c[2 * p + 1] * rs;
                *(float2*)(ob0 + (size_t)(row0 + r) * DIM + col) = o;
            }
        }
    }
}

// ---------------------------------------------------------------------------
extern "C" void kernel_launch(void* const* d_in, const int* in_sizes, int n_in,
                              void* d_out, int out_size)
{
    const float* x          = (const float*)d_in[0];
    const float* mask       = (const float*)d_in[1];
    const float* qkv_w      = (const float*)d_in[2];
    const float* qkv_b      = (const float*)d_in[3];
    const float* proj_w     = (const float*)d_in[4];
    const float* proj_b     = (const float*)d_in[5];
    const float* bias_table = (const float*)d_in[6];
    float* out = (float*)d_out;

    float *qkv_s, *att_s, *biasT_s;
    cudaGetSymbolAddress((void**)&qkv_s, g_qkv);
    cudaGetSymbolAddress((void**)&att_s, g_att);
    cudaGetSymbolAddress((void**)&biasT_s, g_biasT);

    cudaFuncSetAttribute(attn_kernel,
                         cudaFuncAttributeMaxDynamicSharedMemorySize,
                         ATT_SMEM_BYTES);

    // 0) Bias table pre-transpose (tiny)
    bias_transpose_kernel<<<NBIAS, NW * NH>>>(bias_table, biasT_s);

    // 1) QKV projection: (138240 x 192) @ (192 x 576) + b   [tf32 tensor]
    gemm_tf32_kernel<<<dim3(QKV_N / BN, MROWS / BM), 256>>>(
        x, qkv_w, qkv_b, qkv_s, MROWS, QKV_N, DIM);

    // 2) Fused windowed attention per (w, b, h, row-half)   [tf32 tensor]
    attn_kernel<<<dim3(NW, B_LON, NH * 2), 256, ATT_SMEM_BYTES>>>(
        qkv_s, mask, biasT_s, att_s);

    // 3) Output projection: (138240 x 192) @ (192 x 192) + b [tf32 tensor]
    gemm_tf32_kernel<<<dim3(DIM / BN, MROWS / BM), 256>>>(
        att_s, proj_w, proj_b, out, MROWS, DIM, DIM);
}

// round 9
// speedup vs baseline: 2.1345x; 1.2534x over previous
#include <cuda_runtime.h>
#include <cuda_bf16.h>
#include <cstdint>

// Problem constants
#define B_LON   15
#define NW      64
#define NTOK    144
#define DIM     192
#define NH      6
#define HD      32
#define MROWS   (B_LON * NW * NTOK)   // 138240
#define QKV_N   (3 * DIM)             // 576
#define NBIAS   3312
#define RB      72             // rows per attention CTA (half a window)

// Scratch (allocation-free rule: __device__ globals)
__device__ float g_qkv[(size_t)B_LON * NW * NTOK * QKV_N];   // 318 MB
__device__ float g_att[(size_t)B_LON * NW * NTOK * DIM];     // 106 MB
__device__ float g_biasT[(size_t)NW * NH * NBIAS];           // 5 MB: [w*NH+h][idx]

// ---------------------------------------------------------------------------
__global__ void bias_transpose_kernel(const float* __restrict__ bias_table,
                                      float* __restrict__ biasT)
{
    int idx = blockIdx.x;          // 0..3311
    int wh  = threadIdx.x;         // 0..383
    biasT[(size_t)wh * NBIAS + idx] = bias_table[(size_t)idx * (NW * NH) + wh];
}

// ---------------------------------------------------------------------------
// tf32 + cp.async helpers
// ---------------------------------------------------------------------------
__device__ __forceinline__ uint32_t f2tf32(float f) {
    uint32_t u;
    asm("cvt.rna.tf32.f32 %0, %1;" : "=r"(u) : "f"(f));
    return u;
}

__device__ __forceinline__ void mma_tf32(float* c, const uint32_t* a,
                                         const uint32_t* b) {
    asm volatile(
        "mma.sync.aligned.m16n8k8.row.col.f32.tf32.tf32.f32 "
        "{%0,%1,%2,%3}, {%4,%5,%6,%7}, {%8,%9}, {%0,%1,%2,%3};"
        : "+f"(c[0]), "+f"(c[1]), "+f"(c[2]), "+f"(c[3])
        : "r"(a[0]), "r"(a[1]), "r"(a[2]), "r"(a[3]),
          "r"(b[0]), "r"(b[1]));
}

__device__ __forceinline__ void cp16(void* dst, const void* src) {
    uint32_t s = (uint32_t)__cvta_generic_to_shared(dst);
    asm volatile("cp.async.cg.shared.global [%0], [%1], 16;" :: "r"(s), "l"(src));
}
__device__ __forceinline__ void cp_commit() {
    asm volatile("cp.async.commit_group;");
}
template <int N> __device__ __forceinline__ void cp_wait() {
    asm volatile("cp.async.wait_group %0;" :: "n"(N));
}
__device__ __forceinline__ void cp_wait_all() {
    asm volatile("cp.async.wait_all;");
}

// ---------------------------------------------------------------------------
// tf32 tensor-core GEMM + bias, 3-stage cp.async pipeline.
// BM=128, BN=64, BK=16, 256 threads = 8 warps (4M x 2N), warp tile 32x32.
// Raw fp32 in smem; cvt.rna at fragment load. 3 CTAs/SM.
// ---------------------------------------------------------------------------
#define BM 128
#define BN 64
#define BK 16
#define AP 20
#define BP 72
#define NST 3

__global__ __launch_bounds__(256, 3) void gemm_tf32_kernel(
    const float* __restrict__ A, const float* __restrict__ B,
    const float* __restrict__ bias, float* __restrict__ C,
    int M, int N, int K)
{
    __shared__ float As[NST][BM * AP];   // [m][k] fp32
    __shared__ float Bs[NST][BK * BP];   // [k][n] fp32

    const int tid  = threadIdx.x;
    const int lane = tid & 31;
    const int wid  = tid >> 5;
    const int wm   = wid & 3;
    const int wn   = wid >> 2;
    const int grp  = lane >> 2;
    const int tig  = lane & 3;

    const int m0 = blockIdx.y * BM;
    const int n0 = blockIdx.x * BN;

    // A staging: thread -> row ar (0..127), cols ac (0 or 8), two 16B chunks
    const int ar = tid >> 1;
    const int ac = (tid & 1) * 8;
    const float* Ag = A + (size_t)(m0 + ar) * K + ac;
    // B staging: thread -> row bkr (0..15), col bnc, one 16B chunk
    const int bkr = tid >> 4;
    const int bnc = (tid & 15) * 4;
    const float* Bg = B + (size_t)bkr * N + n0 + bnc;

    float acc[2][4][4];
#pragma unroll
    for (int mi = 0; mi < 2; mi++)
#pragma unroll
        for (int ni = 0; ni < 4; ni++)
#pragma unroll
            for (int r = 0; r < 4; r++) acc[mi][ni][r] = 0.0f;

    const int T = K / BK;   // 12

    // Prologue: stage tiles 0 and 1
#pragma unroll
    for (int p = 0; p < 2; p++) {
        const float* a = Ag + p * BK;
        cp16(&As[p][ar * AP + ac],     a);
        cp16(&As[p][ar * AP + ac + 4], a + 4);
        cp16(&Bs[p][bkr * BP + bnc],   Bg + (size_t)p * BK * N);
        cp_commit();
    }

    for (int t = 0; t < T; t++) {
        const int buf = t % NST;
        if (t + 2 < T) {
            const int nb = (t + 2) % NST;
            const float* a = Ag + (t + 2) * BK;
            cp16(&As[nb][ar * AP + ac],     a);
            cp16(&As[nb][ar * AP + ac + 4], a + 4);
            cp16(&Bs[nb][bkr * BP + bnc],   Bg + (size_t)(t + 2) * BK * N);
            cp_commit();
            cp_wait<2>();
        } else if (t + 1 < T) {
            cp_wait<1>();
        } else {
            cp_wait<0>();
        }
        __syncthreads();

        const float* Asb = As[buf];
        const float* Bsb = Bs[buf];
#pragma unroll
        for (int kc = 0; kc < BK; kc += 8) {
            uint32_t af[2][4], bf[4][2];
#pragma unroll
            for (int mi = 0; mi < 2; mi++) {
                int mb = wm * 32 + mi * 16 + grp;
                af[mi][0] = f2tf32(Asb[(mb)     * AP + kc + tig]);
                af[mi][1] = f2tf32(Asb[(mb + 8) * AP + kc + tig]);
                af[mi][2] = f2tf32(Asb[(mb)     * AP + kc + tig + 4]);
                af[mi][3] = f2tf32(Asb[(mb + 8) * AP + kc + tig + 4]);
            }
#pragma unroll
            for (int ni = 0; ni < 4; ni++) {
                int nb = wn * 32 + ni * 8 + grp;
                bf[ni][0] = f2tf32(Bsb[(kc + tig)     * BP + nb]);
                bf[ni][1] = f2tf32(Bsb[(kc + tig + 4) * BP + nb]);
            }
#pragma unroll
            for (int mi = 0; mi < 2; mi++)
#pragma unroll
                for (int ni = 0; ni < 4; ni++)
                    mma_tf32(acc[mi][ni], af[mi], bf[ni]);
        }

        __syncthreads();
    }

#pragma unroll
    for (int mi = 0; mi < 2; mi++) {
        int row = m0 + wm * 32 + mi * 16 + grp;
#pragma unroll
        for (int ni = 0; ni < 4; ni++) {
            int col = n0 + wn * 32 + ni * 8 + 2 * tig;
            float2 bv = *(const float2*)(bias + col);
            float2 o0, o1;
            o0.x = acc[mi][ni][0] + bv.x;
            o0.y = acc[mi][ni][1] + bv.y;
            o1.x = acc[mi][ni][2] + bv.x;
            o1.y = acc[mi][ni][3] + bv.y;
            *(float2*)(C + (size_t)row * N + col)       = o0;
            *(float2*)(C + (size_t)(row + 8) * N + col) = o1;
        }
    }
}

// ---------------------------------------------------------------------------
// Fused attention with tensor-core QK^T and PV (tf32 mma.m16n8k8).
// CTA = (b, w, h, rb): rows [rb*72, rb*72+72).
// q,k,mask,bias staged via cp.async (raw fp32; cvt at fragment load);
// v transposed+converted via register path. Scale folded into S epilogue.
// idx = f(n) + g(m): f = 828*zi + 23*hi + wi ; g = 1656*zj + 138*hj - wj + 11
// smem 110.2 KB -> 2 CTAs/SM.
// ---------------------------------------------------------------------------
#define QP 36     // qS pitch (f32)
#define KP 36     // kS pitch (f32)
#define VP 148    // vT pitch (u32/tf32)
#define SP 164    // S pitch (f32)

#define SM_QS    0                       // [80][36] f32 (rows 72..79 zero)
#define SM_KS    (SM_QS + 80 * QP)       // [144][36] f32
#define SM_VT    (SM_KS + NTOK * KP)     // [32][148] u32
#define SM_S     (SM_VT + 32 * VP)       // [72][164] f32
#define SM_BIAS  (SM_S + RB * SP)        // [3312] f32 (also phantom S rows)
#define SM_RSUM  (SM_BIAS + NBIAS)       // [72] f32
#define SM_FI    (SM_RSUM + RB)          // [72] int
#define SM_GI    (SM_FI + RB)            // [144] int
#define ATT_SMEM_BYTES ((SM_GI + NTOK) * 4)

__global__ __launch_bounds__(256, 2) void attn_kernel(
    const float* __restrict__ qkv, const float* __restrict__ mask,
    const float* __restrict__ biasT, float* __restrict__ out)
{
    extern __shared__ float sm[];
    float*    qSf  = sm + SM_QS;
    float*    kSf  = sm + SM_KS;
    uint32_t* vT   = (uint32_t*)sm + SM_VT;
    float*    S    = sm + SM_S;
    float*    sbias= sm + SM_BIAS;
    float*    rsum = sm + SM_RSUM;
    int*      fI   = (int*)sm + SM_FI;
    int*      gI   = (int*)sm + SM_GI;

    const int w = blockIdx.x, b = blockIdx.y;
    const int h  = blockIdx.z >> 1;
    const int rb = blockIdx.z & 1;
    const int tid  = threadIdx.x;
    const int lane = tid & 31;
    const int wp   = tid >> 5;          // 8 warps
    const int grp  = lane >> 2;         // 0..7
    const int tig  = lane & 3;          // 0..3
    const int bw = b * NW + w;
    const int row0 = rb * RB;
    const float* base = qkv + (size_t)bw * NTOK * QKV_N;
    const float* mbase = mask + (size_t)bw * NTOK * NTOK;
    const float scale = 0.17677669529663687f;  // 1/sqrt(32)

    // ---- cp.async staging: q (local 72 rows), k (all), mask -> S, bias
    for (int idx = tid; idx < RB * 8; idx += 256) {
        int r = idx >> 3, c = (idx & 7) * 4;
        cp16(&qSf[r * QP + c],
             base + (size_t)(row0 + r) * QKV_N + h * HD + c);
    }
    for (int idx = tid; idx < NTOK * 8; idx += 256) {
        int r = idx >> 3, c = (idx & 7) * 4;
        cp16(&kSf[r * KP + c],
             base + (size_t)r * QKV_N + DIM + h * HD + c);
    }
    for (int idx = tid; idx < RB * 36; idx += 256) {
        int r = idx / 36, c = (idx % 36) * 4;
        cp16(&S[r * SP + c], mbase + (size_t)(row0 + r) * NTOK + c);
    }
    {
        const float* bsrc = biasT + (size_t)(w * NH + h) * NBIAS;
        for (int i = tid * 4; i < NBIAS; i += 1024)
            cp16(&sbias[i], bsrc + i);
    }
    cp_commit();

    // ---- v: register path (transpose + tf32 convert), overlaps cp.async
    for (int idx = tid; idx < NTOK * 8; idx += 256) {
        int n = idx >> 3, d = (idx & 7) * 4;
        float4 v4 = *(const float4*)(base + (size_t)n * QKV_N + 2 * DIM
                                     + h * HD + d);
        vT[(d + 0) * VP + n] = f2tf32(v4.x);
        vT[(d + 1) * VP + n] = f2tf32(v4.y);
        vT[(d + 2) * VP + n] = f2tf32(v4.z);
        vT[(d + 3) * VP + n] = f2tf32(v4.w);
    }
    // qS pad rows 72..79 zero
    for (int i = tid; i < 8 * QP; i += 256) qSf[RB * QP + i] = 0.0f;
    // S pad cols 144..159 = -1e30
    for (int idx = tid; idx < RB * 4; idx += 256) {
        int r = idx >> 2, c = 144 + (idx & 3) * 4;
        float4 pv = make_float4(-1e30f, -1e30f, -1e30f, -1e30f);
        *(float4*)&S[r * SP + c] = pv;
    }
    if (tid < RB) {
        int n = row0 + tid;
        int zi = n / 72, hi = (n / 12) % 6, wi = n % 12;
        fI[tid] = 828 * zi + 23 * hi + wi;
    }
    if (tid < NTOK) {
        int zj = tid / 72, hj = (tid / 12) % 6, wj = tid % 12;
        gI[tid] = 1656 * zj + 138 * hj - wj + 11;
    }
    cp_wait_all();
    __syncthreads();

    // ---- Phase 2: S = scale*(q k^T) + bias + mask via mma. 90 tiles.
    for (int t = wp; t < 90; t += 8) {
        int m0 = (t / 18) * 16;
        int n0 = (t % 18) * 8;
        float c[4] = {0.0f, 0.0f, 0.0f, 0.0f};
#pragma unroll
        for (int kc = 0; kc < HD; kc += 8) {
            uint32_t a[4], bfr[2];
            int ab = (m0 + grp) * QP + kc + tig;
            a[0] = f2tf32(qSf[ab]);
            a[1] = f2tf32(qSf[ab + 8 * QP]);
            a[2] = f2tf32(qSf[ab + 4]);
            a[3] = f2tf32(qSf[ab + 8 * QP + 4]);
            int bb = (n0 + grp) * KP + kc + tig;
            bfr[0] = f2tf32(kSf[bb]);
            bfr[1] = f2tf32(kSf[bb + 4]);
            mma_tf32(c, a, bfr);
        }
        int col = n0 + 2 * tig;
        int g0 = gI[col], g1 = gI[col + 1];
#pragma unroll
        for (int p = 0; p < 2; p++) {
            int r = m0 + grp + p * 8;
            if (r < RB) {
                int f = fI[r];
                float* sr = S + r * SP + col;
                sr[0] = fmaf(c[2 * p],     scale, sbias[f + g0] + sr[0]);
                sr[1] = fmaf(c[2 * p + 1], scale, sbias[f + g1] + sr[1]);
            }
        }
    }
    __syncthreads();

    // ---- Phase 3: softmax, warp wp owns rows wp*9..wp*9+8.
    {
#pragma unroll
        for (int i = 0; i < 9; i++) {
            float* row = S + (wp * 9 + i) * SP;
            float v0 = row[lane];
            float v1 = row[lane + 32];
            float v2 = row[lane + 64];
            float v3 = row[lane + 96];
            float v4 = row[lane + 128];          // pad cols hold -1e30
            float mx = fmaxf(fmaxf(fmaxf(v0, v1), fmaxf(v2, v3)), v4);
#pragma unroll
            for (int off = 16; off > 0; off >>= 1)
                mx = fmaxf(mx, __shfl_xor_sync(0xffffffffu, mx, off));
            float e0 = __expf(v0 - mx);
            float e1 = __expf(v1 - mx);
            float e2 = __expf(v2 - mx);
            float e3 = __expf(v3 - mx);
            float e4 = __expf(v4 - mx);
            row[lane]       = e0;
            row[lane + 32]  = e1;
            row[lane + 64]  = e2;
            row[lane + 96]  = e3;
            row[lane + 128] = e4;
            float s = (e0 + e1) + (e2 + e3) + e4;
#pragma unroll
            for (int off = 16; off > 0; off >>= 1)
                s += __shfl_xor_sync(0xffffffffu, s, off);
            if (lane == 0) rsum[wp * 9 + i] = 1.0f / s;
        }
    }
    __syncthreads();

    // ---- Phase 4: O = P v via mma. 20 tiles (5m x 4n), K=144.
    float* ob0 = out + (size_t)bw * NTOK * DIM + h * HD;
    for (int t = wp; t < 20; t += 8) {
        int m0 = (t >> 2) * 16;
        int n0 = (t & 3) * 8;
        float c[4] = {0.0f, 0.0f, 0.0f, 0.0f};
#pragma unroll 6
        for (int kc = 0; kc < NTOK; kc += 8) {
            uint32_t a[4], bfr[2];
            const float* ap = S + (m0 + grp) * SP + kc + tig;
            a[0] = f2tf32(ap[0]);
            a[1] = f2tf32(ap[8 * SP]);
            a[2] = f2tf32(ap[4]);
            a[3] = f2tf32(ap[8 * SP + 4]);
            int bb = (n0 + grp) * VP + kc + tig;
            bfr[0] = vT[bb];
            bfr[1] = vT[bb + 4];
            mma_tf32(c, a, bfr);
        }
        int col = n0 + 2 * tig;
#pragma unroll
        for (int p = 0; p < 2; p++) {
            int r = m0 + grp + p * 8;
            if (r < RB) {
                float rs = rsum[r];
                float2 o;
                o.x = c[2 * p] * rs;
                o.y = c[2 * p + 1] * rs;
                *(float2*)(ob0 + (size_t)(row0 + r) * DIM + col) = o;
            }
        }
    }
}

// ---------------------------------------------------------------------------
extern "C" void kernel_launch(void* const* d_in, const int* in_sizes, int n_in,
                              void* d_out, int out_size)
{
    const float* x          = (const float*)d_in[0];
    const float* mask       = (const float*)d_in[1];
    const float* qkv_w      = (const float*)d_in[2];
    const float* qkv_b      = (const float*)d_in[3];
    const float* proj_w     = (const float*)d_in[4];
    const float* proj_b     = (const float*)d_in[5];
    const float* bias_table = (const float*)d_in[6];
    float* out = (float*)d_out;

    float *qkv_s, *att_s, *biasT_s;
    cudaGetSymbolAddress((void**)&qkv_s, g_qkv);
    cudaGetSymbolAddress((void**)&att_s, g_att);
    cudaGetSymbolAddress((void**)&biasT_s, g_biasT);

    cudaFuncSetAttribute(attn_kernel,
                         cudaFuncAttributeMaxDynamicSharedMemorySize,
                         ATT_SMEM_BYTES);

    // 0) Bias table pre-transpose (tiny)
    bias_transpose_kernel<<<NBIAS, NW * NH>>>(bias_table, biasT_s);

    // 1) QKV projection: (138240 x 192) @ (192 x 576) + b   [tf32 tensor]
    gemm_tf32_kernel<<<dim3(QKV_N / BN, MROWS / BM), 256>>>(
        x, qkv_w, qkv_b, qkv_s, MROWS, QKV_N, DIM);

    // 2) Fused windowed attention per (w, b, h, row-half)   [tf32 tensor]
    attn_kernel<<<dim3(NW, B_LON, NH * 2), 256, ATT_SMEM_BYTES>>>(
        qkv_s, mask, biasT_s, att_s);

    // 3) Output projection: (138240 x 192) @ (192 x 192) + b [tf32 tensor]
    gemm_tf32_kernel<<<dim3(DIM / BN, MROWS / BM), 256>>>(
        att_s, proj_w, proj_b, out, MROWS, DIM, DIM);
}